// round 11
// baseline (speedup 1.0000x reference)
#include <cuda_runtime.h>

typedef unsigned int u32;

// CostVolume via banded tf32 GEMM (mma.sync m16n8k8) with cp.async fills.
// Block = (bh, 128-w tile), 256 threads / 8 warps.
// Warp (g = wid>>1, h = wid&1): G[32, 48] = L[rows 32g..+31, :] .
//   R[rows 32g+48h .. +47, :]^T   (R row r <-> src = w0-64+r)
// out[w,d] = G_band / 64, masked where src = w-1-d < 0.
//
// Channels split in two 32-ch chunks, each in its own smem buffer; raw fp32
// is cp.async'd to smem (no register staging), tf32 conversion happens on
// the fragments (bit-identical to converting at fill). Both chunks' copies
// are in flight before compute starts.

namespace {
constexpr int Wd = 512, Cd = 64, Dd = 64, WT = 128;
constexpr int P         = 40;                 // smem pitch (words) per chunk
constexpr int L_WORDS   = 128 * P;            // 5120
constexpr int R_WORDS   = 192 * P;            // 7680
constexpr int BUF_WORDS = L_WORDS + R_WORDS;  // 12800
constexpr int SMEM_BYTES = 2 * BUF_WORDS * 4; // 102,400
constexpr int STG_P     = 68;                 // staging pitch (words)
}

__device__ __forceinline__ u32 smem_u32(const void* p) {
    u32 a;
    asm("{ .reg .u64 t; cvta.to.shared.u64 t, %1; cvt.u32.u64 %0, t; }" : "=r"(a) : "l"(p));
    return a;
}
__device__ __forceinline__ void cp16(u32 saddr, const void* g) {
    asm volatile("cp.async.cg.shared.global [%0], [%1], 16;" :: "r"(saddr), "l"(g));
}
__device__ __forceinline__ u32 f2tf32(float x) {
    u32 r;
    asm("cvt.rna.tf32.f32 %0, %1;" : "=r"(r) : "f"(x));
    return r;
}
__device__ __forceinline__ u32 cvt_u(u32 raw) { return f2tf32(__uint_as_float(raw)); }

__device__ __forceinline__ void mma_tf32(float* d, const u32* a, u32 b0, u32 b1) {
    asm("mma.sync.aligned.m16n8k8.row.col.f32.tf32.tf32.f32 "
        "{%0,%1,%2,%3}, {%4,%5,%6,%7}, {%8,%9}, {%0,%1,%2,%3};"
        : "+f"(d[0]), "+f"(d[1]), "+f"(d[2]), "+f"(d[3])
        : "r"(a[0]), "r"(a[1]), "r"(a[2]), "r"(a[3]), "r"(b0), "r"(b1));
}

__global__ __launch_bounds__(256, 2)
void cost_volume_mma_kernel(const float* __restrict__ left,
                            const float* __restrict__ right,
                            float* __restrict__ out) {
    extern __shared__ u32 sm[];
    const u32 sbase = smem_u32(sm);

    const int tid  = threadIdx.x;
    const int wid  = tid >> 5;        // 0..7
    const int lane = tid & 31;
    const int g    = wid >> 1;        // row group 0..3 (32 rows each)
    const int h    = wid & 1;         // col half 0..1 (48 cols each)
    const int q    = lane >> 2;       // 0..7
    const int c    = lane & 3;        // 0..3
    const int w0   = blockIdx.x * WT;
    const int bh   = blockIdx.y;

    const float* lrow = left  + (size_t)bh * Wd * Cd;
    const float* rrow = right + (size_t)bh * Wd * Cd;

    // ---- fill both 32-channel chunks via cp.async (2 commit groups) ----
    {
        const int row = tid >> 3;          // base row (L:+32i, R:+32i)
        const int c4  = tid & 7;           // 16B column chunk
#pragma unroll
        for (int ch = 0; ch < 2; ch++) {
            const int cb = 32 * ch;
            const u32 buf = sbase + (u32)(ch * BUF_WORDS * 4);
#pragma unroll
            for (int i = 0; i < 4; i++) {
                const int r = row + 32 * i;
                cp16(buf + (u32)((r * P + 4 * c4) * 4),
                     lrow + (size_t)(w0 + r) * Cd + cb + 4 * c4);
            }
#pragma unroll
            for (int i = 0; i < 6; i++) {
                const int r = row + 32 * i;
                const int s = max(w0 - 64 + r, 0);     // clamped; masked later
                cp16(buf + (u32)((L_WORDS + r * P + 4 * c4) * 4),
                     rrow + (size_t)s * Cd + cb + 4 * c4);
            }
            asm volatile("cp.async.commit_group;" ::: "memory");
        }
    }

    float acc[2][6][4];
#pragma unroll
    for (int mt = 0; mt < 2; mt++)
#pragma unroll
        for (int nt = 0; nt < 6; nt++)
#pragma unroll
            for (int r = 0; r < 4; r++) acc[mt][nt][r] = 0.0f;

    const int la_off = (32 * g + q) * P;
    const int rb_off = L_WORDS + (32 * g + 48 * h + q) * P;

    // ---- compute: 2 chunks x 4 K-steps of 8 (fragments cvt'd to tf32) ----
#pragma unroll
    for (int ch = 0; ch < 2; ch++) {
        if (ch == 0) asm volatile("cp.async.wait_group 1;" ::: "memory");
        else         asm volatile("cp.async.wait_group 0;" ::: "memory");
        __syncthreads();

        const u32* buf = sm + ch * BUF_WORDS;
        const u32* la_base = buf + la_off;
        const u32* rb_base = buf + rb_off;
#pragma unroll
        for (int ks = 0; ks < 4; ks++) {
            const int kb = 8 * ks + 2 * c;
            u32 a[2][4];
#pragma unroll
            for (int mt = 0; mt < 2; mt++) {
                const uint2 lo = *(const uint2*)(la_base + (16 * mt) * P + kb);
                const uint2 hi = *(const uint2*)(la_base + (16 * mt + 8) * P + kb);
                a[mt][0] = cvt_u(lo.x); a[mt][2] = cvt_u(lo.y);
                a[mt][1] = cvt_u(hi.x); a[mt][3] = cvt_u(hi.y);
            }
#pragma unroll
            for (int nt = 0; nt < 6; nt++) {
                const uint2 bb = *(const uint2*)(rb_base + (8 * nt) * P + kb);
                const u32 b0 = cvt_u(bb.x), b1 = cvt_u(bb.y);
                mma_tf32(acc[0][nt], a[0], b0, b1);
                mma_tf32(acc[1][nt], a[1], b0, b1);
            }
        }
    }

    // ---- epilogue: diagonal extraction into smem staging ----
    __syncthreads();
    float* stage = (float*)sm;                    // [128][STG_P], reuses buffer0
    const float scale = 1.0f / 64.0f;
#pragma unroll
    for (int mt = 0; mt < 2; mt++)
#pragma unroll
        for (int nt = 0; nt < 6; nt++)
#pragma unroll
            for (int r = 0; r < 4; r++) {
                const int d = 63 + 16 * mt + 8 * (r >> 1) + q
                              - 48 * h - 8 * nt - 2 * c - (r & 1);
                if (d >= 0 && d < 64) {
                    const int w_l = 32 * g + 16 * mt + 8 * (r >> 1) + q;
                    const int s_l = w_l + 63 - d;
                    const float val = (w0 + s_l >= 64) ? acc[mt][nt][r] * scale : 0.0f;
                    stage[w_l * STG_P + d] = val;
                }
            }
    __syncthreads();

    // ---- coalesced copy staging -> gmem ----
#pragma unroll
    for (int i = 0; i < 8; i++) {
        const int idx = tid + 256 * i;           // 0..2047
        const int row = idx >> 4, c4 = idx & 15;
        const float4 v = *(const float4*)(stage + row * STG_P + 4 * c4);
        *(float4*)(out + ((size_t)bh * Wd + w0 + row) * Dd + 4 * c4) = v;
    }
}

extern "C" void kernel_launch(void* const* d_in, const int* in_sizes, int n_in,
                              void* d_out, int out_size) {
    const float* left  = (const float*)d_in[0];
    const float* right = (const float*)d_in[1];
    float* outp = (float*)d_out;

    const int BH = in_sizes[0] / (Wd * Cd);

    cudaFuncSetAttribute(cost_volume_mma_kernel,
                         cudaFuncAttributeMaxDynamicSharedMemorySize, SMEM_BYTES);
    dim3 grid(Wd / WT, BH, 1);
    cost_volume_mma_kernel<<<grid, 256, SMEM_BYTES>>>(left, right, outp);
}

// round 12
// speedup vs baseline: 1.0372x; 1.0372x over previous
#include <cuda_runtime.h>

typedef unsigned int u32;

// CostVolume via banded tf32 GEMM (mma.sync m16n8k8), pipelined cp.async.
// Grid 2048 = (bh, half-row). Block = 256 threads / 8 warps, processes
// 2 w-tiles x 2 channel-chunks = 4 stages through a 2-deep smem ring.
// Warp (g = wid>>1, h = wid&1): G[32, 48] = L[rows 32g..+31] . R[rows
// 32g+48h..+47]^T  (R row r <-> src = w0-64+r).
// out[w,d] = G_band / 64, masked where src = w-1-d < 0.

namespace {
constexpr int Wd = 512, Cd = 64, Dd = 64, WT = 128;
constexpr int P         = 40;                 // smem pitch (words) per chunk
constexpr int L_WORDS   = 128 * P;            // 5120
constexpr int R_WORDS   = 192 * P;            // 7680
constexpr int BUF_WORDS = L_WORDS + R_WORDS;  // 12800
constexpr int SMEM_BYTES = 2 * BUF_WORDS * 4; // 102,400
constexpr int STG_P     = 68;                 // out staging pitch (words)
constexpr int NSTAGE    = 4;                  // 2 tiles x 2 chunks
}

__device__ __forceinline__ u32 smem_u32(const void* p) {
    u32 a;
    asm("{ .reg .u64 t; cvta.to.shared.u64 t, %1; cvt.u32.u64 %0, t; }" : "=r"(a) : "l"(p));
    return a;
}
__device__ __forceinline__ void cp16(u32 saddr, const void* g) {
    asm volatile("cp.async.cg.shared.global [%0], [%1], 16;" :: "r"(saddr), "l"(g));
}
__device__ __forceinline__ u32 f2tf32(float x) {
    u32 r;
    asm("cvt.rna.tf32.f32 %0, %1;" : "=r"(r) : "f"(x));
    return r;
}
__device__ __forceinline__ u32 cvt_u(u32 raw) { return f2tf32(__uint_as_float(raw)); }

__device__ __forceinline__ void mma_tf32(float* d, const u32* a, u32 b0, u32 b1) {
    asm("mma.sync.aligned.m16n8k8.row.col.f32.tf32.tf32.f32 "
        "{%0,%1,%2,%3}, {%4,%5,%6,%7}, {%8,%9}, {%0,%1,%2,%3};"
        : "+f"(d[0]), "+f"(d[1]), "+f"(d[2]), "+f"(d[3])
        : "r"(a[0]), "r"(a[1]), "r"(a[2]), "r"(a[3]), "r"(b0), "r"(b1));
}

__global__ __launch_bounds__(256, 2)
void cost_volume_mma_kernel(const float* __restrict__ left,
                            const float* __restrict__ right,
                            float* __restrict__ out) {
    extern __shared__ u32 sm[];
    const u32 sbase = smem_u32(sm);

    const int tid  = threadIdx.x;
    const int wid  = tid >> 5;        // 0..7
    const int lane = tid & 31;
    const int g    = wid >> 1;        // row group 0..3 (32 rows each)
    const int h    = wid & 1;         // col half 0..1 (48 cols each)
    const int q    = lane >> 2;       // 0..7
    const int c    = lane & 3;        // 0..3

    const int bx   = blockIdx.x;
    const int bh   = bx >> 1;
    const int half = bx & 1;

    const float* lrow = left  + (size_t)bh * Wd * Cd;
    const float* rrow = right + (size_t)bh * Wd * Cd;

    const int frow = tid >> 3;        // fill base row
    const int fc4  = tid & 7;         // fill 16B column chunk

    // stage s: tile = 2*half + (s>>1), chunk = s&1, buffer = s&1
#define PREFETCH(s)                                                            \
    {                                                                          \
        const int w0p = (2 * half + ((s) >> 1)) * WT;                          \
        const int cbp = ((s) & 1) * 32;                                        \
        const u32 buf = sbase + (u32)((((s) & 1) * BUF_WORDS) * 4);            \
        _Pragma("unroll")                                                      \
        for (int i = 0; i < 4; i++) {                                          \
            const int r = frow + 32 * i;                                       \
            cp16(buf + (u32)((r * P + 4 * fc4) * 4),                           \
                 lrow + (size_t)(w0p + r) * Cd + cbp + 4 * fc4);               \
        }                                                                      \
        _Pragma("unroll")                                                      \
        for (int i = 0; i < 6; i++) {                                          \
            const int r = frow + 32 * i;                                       \
            const int sg = max(w0p - 64 + r, 0);                               \
            cp16(buf + (u32)((L_WORDS + r * P + 4 * fc4) * 4),                 \
                 rrow + (size_t)sg * Cd + cbp + 4 * fc4);                      \
        }                                                                      \
        asm volatile("cp.async.commit_group;" ::: "memory");                   \
    }

    PREFETCH(0);

    float acc[2][6][4];
    const int la_off = (32 * g + q) * P;
    const int rb_off = L_WORDS + (32 * g + 48 * h + q) * P;
    const float scale = 1.0f / 64.0f;

#pragma unroll
    for (int s = 0; s < NSTAGE; s++) {
        if ((s & 1) == 0) {           // new tile -> clear accumulators
#pragma unroll
            for (int mt = 0; mt < 2; mt++)
#pragma unroll
                for (int nt = 0; nt < 6; nt++)
#pragma unroll
                    for (int r = 0; r < 4; r++) acc[mt][nt][r] = 0.0f;
        }

        if (s + 1 < NSTAGE) {
            PREFETCH(s + 1);
            asm volatile("cp.async.wait_group 1;" ::: "memory");
        } else {
            asm volatile("cp.async.wait_group 0;" ::: "memory");
        }
        __syncthreads();

        // ---- compute stage s: 4 K-steps of 8, fragments cvt'd to tf32 ----
        const u32* buf = sm + (s & 1) * BUF_WORDS;
        const u32* la_base = buf + la_off;
        const u32* rb_base = buf + rb_off;
#pragma unroll
        for (int ks = 0; ks < 4; ks++) {
            const int kb = 8 * ks + 2 * c;
            u32 a[2][4];
#pragma unroll
            for (int mt = 0; mt < 2; mt++) {
                const uint2 lo = *(const uint2*)(la_base + (16 * mt) * P + kb);
                const uint2 hi = *(const uint2*)(la_base + (16 * mt + 8) * P + kb);
                a[mt][0] = cvt_u(lo.x); a[mt][2] = cvt_u(lo.y);
                a[mt][1] = cvt_u(hi.x); a[mt][3] = cvt_u(hi.y);
            }
#pragma unroll
            for (int nt = 0; nt < 6; nt++) {
                const uint2 bb = *(const uint2*)(rb_base + (8 * nt) * P + kb);
                const u32 b0 = cvt_u(bb.x), b1 = cvt_u(bb.y);
                mma_tf32(acc[0][nt], a[0], b0, b1);
                mma_tf32(acc[1][nt], a[1], b0, b1);
            }
        }
        __syncthreads();              // all reads of buf[s&1] done

        if (s & 1) {
            // ---- tile epilogue: stage diagonals in the dead buffer ----
            const int w0 = (2 * half + (s >> 1)) * WT;
            float* stage = (float*)(sm + (s & 1) * BUF_WORDS);
#pragma unroll
            for (int mt = 0; mt < 2; mt++)
#pragma unroll
                for (int nt = 0; nt < 6; nt++)
#pragma unroll
                    for (int r = 0; r < 4; r++) {
                        const int d = 63 + 16 * mt + 8 * (r >> 1) + q
                                      - 48 * h - 8 * nt - 2 * c - (r & 1);
                        if (d >= 0 && d < 64) {
                            const int w_l = 32 * g + 16 * mt + 8 * (r >> 1) + q;
                            const int s_l = w_l + 63 - d;
                            const float val =
                                (w0 + s_l >= 64) ? acc[mt][nt][r] * scale : 0.0f;
                            stage[w_l * STG_P + d] = val;
                        }
                    }
            __syncthreads();
            // coalesced copy staging -> gmem
#pragma unroll
            for (int i = 0; i < 8; i++) {
                const int idx = tid + 256 * i;     // 0..2047
                const int row = idx >> 4, c4 = idx & 15;
                const float4 v = *(const float4*)(stage + row * STG_P + 4 * c4);
                *(float4*)(out + ((size_t)bh * Wd + w0 + row) * Dd + 4 * c4) = v;
            }
            __syncthreads();          // staging reads done before buf reuse
        }
    }
#undef PREFETCH
}

extern "C" void kernel_launch(void* const* d_in, const int* in_sizes, int n_in,
                              void* d_out, int out_size) {
    const float* left  = (const float*)d_in[0];
    const float* right = (const float*)d_in[1];
    float* outp = (float*)d_out;

    const int BH = in_sizes[0] / (Wd * Cd);

    cudaFuncSetAttribute(cost_volume_mma_kernel,
                         cudaFuncAttributeMaxDynamicSharedMemorySize, SMEM_BYTES);
    dim3 grid(BH * 2, 1, 1);
    cost_volume_mma_kernel<<<grid, 256, SMEM_BYTES>>>(left, right, outp);
}